// round 1
// baseline (speedup 1.0000x reference)
#include <cuda_runtime.h>
#include <math.h>

#define NN    20
#define INDIM 9
#define HID   128
#define KNN   5
#define STRIDE 132   // 128 + 4 pad: conflict-free column walks, keeps 16B alignment for k%4==0

__device__ __forceinline__ float gelu_exact(float x) {
    return 0.5f * x * (1.0f + erff(x * 0.70710678118654752440f));
}

// Warp-cooperative LayerNorm stats: warp w handles nodes [5w, 5w+5).
// Two-pass (mean, then centered variance) for numerical safety.
__device__ __forceinline__ void ln_stats(const float* __restrict__ buf,
                                         float* __restrict__ st_m,
                                         float* __restrict__ st_r,
                                         int tid) {
    const int w = tid >> 5, lane = tid & 31;
    #pragma unroll
    for (int ii = 0; ii < 5; ++ii) {
        const int i = w * 5 + ii;
        const float* row = buf + i * STRIDE;
        float a0 = row[lane], a1 = row[lane + 32], a2 = row[lane + 64], a3 = row[lane + 96];
        float s = (a0 + a1) + (a2 + a3);
        #pragma unroll
        for (int off = 16; off; off >>= 1) s += __shfl_xor_sync(0xffffffffu, s, off);
        float m = s * (1.0f / 128.0f);
        float q0 = a0 - m, q1 = a1 - m, q2 = a2 - m, q3 = a3 - m;
        float q = q0 * q0 + q1 * q1 + q2 * q2 + q3 * q3;
        #pragma unroll
        for (int off = 16; off; off >>= 1) q += __shfl_xor_sync(0xffffffffu, q, off);
        if (lane == 0) {
            st_m[i] = m;
            st_r[i] = rsqrtf(q * (1.0f / 128.0f) + 1e-5f);
        }
    }
}

__global__ __launch_bounds__(128, 4)
void hbond_gnn_fused(const float* __restrict__ x_all,
                     const float* __restrict__ w_embed,
                     const float* __restrict__ b_embed,
                     const float* __restrict__ w1,
                     const float* __restrict__ b1,
                     const float* __restrict__ w2,
                     const float* __restrict__ b2,
                     const float* __restrict__ g1,
                     const float* __restrict__ be1,
                     const float* __restrict__ g2,
                     const float* __restrict__ be2,
                     float* __restrict__ out) {
    __shared__ float xs[NN * INDIM];
    __shared__ __align__(16) float bufA[NN * STRIDE];
    __shared__ __align__(16) float bufB[NN * STRIDE];
    __shared__ float d2s[NN * NN];
    __shared__ int   nbr[NN * KNN];
    __shared__ float st_m[NN], st_r[NN];

    const int tid = threadIdx.x;
    const int b = blockIdx.x;
    const float* x = x_all + (size_t)b * (NN * INDIM);

    // ---- load node features ----
    for (int t = tid; t < NN * INDIM; t += 128) xs[t] = x[t];
    __syncthreads();

    // ---- pairwise squared distances on pos = features [6,9) ----
    for (int t = tid; t < NN * NN; t += 128) {
        const int i = t / NN, j = t % NN;
        float dx = xs[i * INDIM + 6] - xs[j * INDIM + 6];
        float dy = xs[i * INDIM + 7] - xs[j * INDIM + 7];
        float dz = xs[i * INDIM + 8] - xs[j * INDIM + 8];
        d2s[t] = (dx * dx + dy * dy) + dz * dz;
    }
    __syncthreads();

    // ---- top-5 smallest d2 per row; ties -> lower index (matches lax.top_k) ----
    if (tid < NN) {
        const int i = tid;
        unsigned mask = 0;
        for (int r = 0; r < KNN; ++r) {
            float best = 3.4e38f; int bj = 0;
            #pragma unroll
            for (int j = 0; j < NN; ++j) {
                float v = d2s[i * NN + j];
                if (!((mask >> j) & 1u) && v < best) { best = v; bj = j; }
            }
            mask |= 1u << bj;
            nbr[i * KNN + r] = bj;
        }
    }

    // ---- embedding: h0 = x @ w_embed + b_embed  -> bufA ----
    {
        float we[INDIM];
        #pragma unroll
        for (int f = 0; f < INDIM; ++f) we[f] = w_embed[f * HID + tid];
        const float bev = b_embed[tid];
        #pragma unroll
        for (int i = 0; i < NN; ++i) {
            float s = bev;
            #pragma unroll
            for (int f = 0; f < INDIM; ++f) s = fmaf(xs[i * INDIM + f], we[f], s);
            bufA[i * STRIDE + tid] = s;
        }
    }
    __syncthreads();

    // ---- agg1: bufB = adj @ bufA ----
    #pragma unroll
    for (int i = 0; i < NN; ++i) {
        float s = 0.0f;
        #pragma unroll
        for (int r = 0; r < KNN; ++r) s += bufA[nbr[i * KNN + r] * STRIDE + tid];
        bufB[i * STRIDE + tid] = s;
    }
    __syncthreads();

    float acc[NN];

    // ---- GEMM1: acc = bufB @ w1 + b1 (thread = output column, 20 rows/thread) ----
    {
        const float bv = b1[tid];
        #pragma unroll
        for (int i = 0; i < NN; ++i) acc[i] = bv;
        const float* wc = w1 + tid;
        #pragma unroll 2
        for (int k = 0; k < HID; k += 4) {
            const float w0 = wc[(k + 0) * HID];
            const float wv1 = wc[(k + 1) * HID];
            const float wv2 = wc[(k + 2) * HID];
            const float wv3 = wc[(k + 3) * HID];
            #pragma unroll
            for (int i = 0; i < NN; ++i) {
                float4 a = *reinterpret_cast<const float4*>(&bufB[i * STRIDE + k]);
                float s = acc[i];
                s = fmaf(a.x, w0, s);
                s = fmaf(a.y, wv1, s);
                s = fmaf(a.z, wv2, s);
                s = fmaf(a.w, wv3, s);
                acc[i] = s;
            }
        }
    }
    #pragma unroll
    for (int i = 0; i < NN; ++i) bufA[i * STRIDE + tid] = acc[i];
    __syncthreads();

    ln_stats(bufA, st_m, st_r, tid);
    __syncthreads();

    // ---- LN1 + GeLU -> h1 (regs) and bufB ----
    float h1r[NN];
    {
        const float g = g1[tid], bb = be1[tid];
        #pragma unroll
        for (int i = 0; i < NN; ++i) {
            float v = (acc[i] - st_m[i]) * st_r[i] * g + bb;
            float hv = gelu_exact(v);
            h1r[i] = hv;
            bufB[i * STRIDE + tid] = hv;
        }
    }
    __syncthreads();

    // ---- agg2: bufA = adj @ bufB ----
    #pragma unroll
    for (int i = 0; i < NN; ++i) {
        float s = 0.0f;
        #pragma unroll
        for (int r = 0; r < KNN; ++r) s += bufB[nbr[i * KNN + r] * STRIDE + tid];
        bufA[i * STRIDE + tid] = s;
    }
    __syncthreads();

    // ---- GEMM2: acc = bufA @ w2 + b2 ----
    {
        const float bv = b2[tid];
        #pragma unroll
        for (int i = 0; i < NN; ++i) acc[i] = bv;
        const float* wc = w2 + tid;
        #pragma unroll 2
        for (int k = 0; k < HID; k += 4) {
            const float w0 = wc[(k + 0) * HID];
            const float wv1 = wc[(k + 1) * HID];
            const float wv2 = wc[(k + 2) * HID];
            const float wv3 = wc[(k + 3) * HID];
            #pragma unroll
            for (int i = 0; i < NN; ++i) {
                float4 a = *reinterpret_cast<const float4*>(&bufA[i * STRIDE + k]);
                float s = acc[i];
                s = fmaf(a.x, w0, s);
                s = fmaf(a.y, wv1, s);
                s = fmaf(a.z, wv2, s);
                s = fmaf(a.w, wv3, s);
                acc[i] = s;
            }
        }
    }
    __syncthreads();          // all GEMM2 reads of bufA/bufB done before reuse
    #pragma unroll
    for (int i = 0; i < NN; ++i) bufB[i * STRIDE + tid] = acc[i];
    __syncthreads();

    ln_stats(bufB, st_m, st_r, tid);
    __syncthreads();

    // ---- LN2 + residual + GeLU + node-max ----
    {
        const float g = g2[tid], bb = be2[tid];
        float mx = -3.4e38f;
        #pragma unroll
        for (int i = 0; i < NN; ++i) {
            float v = (acc[i] - st_m[i]) * st_r[i] * g + bb;
            float hv = gelu_exact(h1r[i] + v);
            mx = fmaxf(mx, hv);
        }
        out[(size_t)b * HID + tid] = mx;
    }
}

extern "C" void kernel_launch(void* const* d_in, const int* in_sizes, int n_in,
                              void* d_out, int out_size) {
    const float* x_all   = (const float*)d_in[0];
    const float* w_embed = (const float*)d_in[1];
    const float* b_embed = (const float*)d_in[2];
    const float* w1      = (const float*)d_in[3];
    const float* b1      = (const float*)d_in[4];
    const float* w2      = (const float*)d_in[5];
    const float* b2      = (const float*)d_in[6];
    const float* g1      = (const float*)d_in[7];
    const float* be1     = (const float*)d_in[8];
    const float* g2      = (const float*)d_in[9];
    const float* be2     = (const float*)d_in[10];
    float* out = (float*)d_out;

    const int B = in_sizes[0] / (NN * INDIM);

    hbond_gnn_fused<<<B, 128>>>(x_all, w_embed, b_embed, w1, b1, w2, b2,
                                g1, be1, g2, be2, out);
}

// round 3
// speedup vs baseline: 1.1173x; 1.1173x over previous
#include <cuda_runtime.h>
#include <math.h>

#define NN    20
#define INDIM 9
#define HID   128
#define KNN   5
#define STRIDE 132   // 128 + 4 pad; row stride 528B is 16B-aligned

typedef unsigned long long u64;

// k-pair packed weights: Wp[kp][c] = (W[2kp][c], W[2kp+1][c])
__device__ __align__(16) float2 g_Wp1[64 * HID];
__device__ __align__(16) float2 g_Wp2[64 * HID];

__global__ void prep_weights(const float* __restrict__ w1, const float* __restrict__ w2) {
    int t = blockIdx.x * blockDim.x + threadIdx.x;
    if (t < 64 * HID) {
        int kp = t / HID, c = t % HID;
        g_Wp1[t] = make_float2(w1[(2 * kp) * HID + c], w1[(2 * kp + 1) * HID + c]);
        g_Wp2[t] = make_float2(w2[(2 * kp) * HID + c], w2[(2 * kp + 1) * HID + c]);
    }
}

__device__ __forceinline__ void ffma2(u64& d, u64 a, u64 b) {
    asm("fma.rn.f32x2 %0, %1, %2, %0;" : "+l"(d) : "l"(a), "l"(b));
}

__device__ __forceinline__ float gelu_exact(float x) {
    return 0.5f * x * (1.0f + erff(x * 0.70710678118654752440f));
}

// C[20x128] = A[20x128] @ W + bias handled by caller.
// Thread (rt=tid>>5, ct=tid&31) computes rows r0..r0+4, cols c0..c0+3.
// A rows are warp-uniform -> LDS broadcasts. W from k-pair packed gmem (L1-hot).
__device__ __forceinline__ void gemm20(const float* __restrict__ A,
                                       const float2* __restrict__ Wp,
                                       int r0, int c0, u64 acc[20]) {
    #pragma unroll
    for (int i = 0; i < 20; ++i) acc[i] = 0ull;
    #pragma unroll 2
    for (int kq = 0; kq < 32; ++kq) {          // 4 k's per iter = 2 k-pairs
        u64 a[5][2];
        #pragma unroll
        for (int r = 0; r < 5; ++r) {
            ulonglong2 t = *reinterpret_cast<const ulonglong2*>(&A[(r0 + r) * STRIDE + 4 * kq]);
            a[r][0] = t.x; a[r][1] = t.y;
        }
        #pragma unroll
        for (int kk = 0; kk < 2; ++kk) {
            const float2* wrow = Wp + (2 * kq + kk) * HID + c0;
            ulonglong2 w01 = *reinterpret_cast<const ulonglong2*>(wrow);
            ulonglong2 w23 = *reinterpret_cast<const ulonglong2*>(wrow + 2);
            u64 wv0 = w01.x, wv1 = w01.y, wv2 = w23.x, wv3 = w23.y;
            #pragma unroll
            for (int r = 0; r < 5; ++r) {
                ffma2(acc[r * 4 + 0], a[r][kk], wv0);
                ffma2(acc[r * 4 + 1], a[r][kk], wv1);
                ffma2(acc[r * 4 + 2], a[r][kk], wv2);
                ffma2(acc[r * 4 + 3], a[r][kk], wv3);
            }
        }
    }
}

// LayerNorm stats via warp shuffles: warp owns 5 full rows (lanes cover all 128 cols).
__device__ __forceinline__ void ln_warp(const float v[20], float m[5], float rs[5]) {
    #pragma unroll
    for (int r = 0; r < 5; ++r) {
        float s = (v[r * 4] + v[r * 4 + 1]) + (v[r * 4 + 2] + v[r * 4 + 3]);
        #pragma unroll
        for (int off = 16; off; off >>= 1) s += __shfl_xor_sync(0xffffffffu, s, off);
        float mean = s * (1.0f / 128.0f);
        float q = 0.0f;
        #pragma unroll
        for (int c = 0; c < 4; ++c) { float d = v[r * 4 + c] - mean; q = fmaf(d, d, q); }
        #pragma unroll
        for (int off = 16; off; off >>= 1) q += __shfl_xor_sync(0xffffffffu, q, off);
        m[r]  = mean;
        rs[r] = rsqrtf(q * (1.0f / 128.0f) + 1e-5f);
    }
}

__global__ __launch_bounds__(128, 4)
void hbond_gnn_fused(const float* __restrict__ x_all,
                     const float* __restrict__ w_embed,
                     const float* __restrict__ b_embed,
                     const float* __restrict__ b1,
                     const float* __restrict__ b2,
                     const float* __restrict__ g1,
                     const float* __restrict__ be1,
                     const float* __restrict__ g2,
                     const float* __restrict__ be2,
                     float* __restrict__ out) {
    __shared__ float xs[NN * INDIM];
    __shared__ __align__(16) float bufA[NN * STRIDE];
    __shared__ __align__(16) float bufB[NN * STRIDE];
    __shared__ float d2s[NN * NN];
    __shared__ int   nbr[NN * KNN];
    __shared__ __align__(16) float pmax[4 * HID];

    const int tid = threadIdx.x;
    const int rt = tid >> 5, ct = tid & 31;
    const int r0 = rt * 5, c0 = ct * 4;
    const int b = blockIdx.x;
    const float* x = x_all + (size_t)b * (NN * INDIM);

    // ---- load node features ----
    for (int t = tid; t < NN * INDIM; t += 128) xs[t] = x[t];
    __syncthreads();

    // ---- pairwise squared distances on pos = features [6,9) ----
    for (int t = tid; t < NN * NN; t += 128) {
        const int i = t / NN, j = t % NN;
        float dx = xs[i * INDIM + 6] - xs[j * INDIM + 6];
        float dy = xs[i * INDIM + 7] - xs[j * INDIM + 7];
        float dz = xs[i * INDIM + 8] - xs[j * INDIM + 8];
        d2s[t] = (dx * dx + dy * dy) + dz * dz;
    }
    __syncthreads();

    // ---- top-5 nearest per row; ties -> lower index (matches lax.top_k) ----
    if (tid < NN) {
        const int i = tid;
        unsigned mask = 0;
        for (int r = 0; r < KNN; ++r) {
            float best = 3.4e38f; int bj = 0;
            #pragma unroll
            for (int j = 0; j < NN; ++j) {
                float v = d2s[i * NN + j];
                if (!((mask >> j) & 1u) && v < best) { best = v; bj = j; }
            }
            mask |= 1u << bj;
            nbr[i * KNN + r] = bj;
        }
    }

    // ---- embedding (column layout: thread = column tid) -> bufA ----
    {
        float we[INDIM];
        #pragma unroll
        for (int f = 0; f < INDIM; ++f) we[f] = w_embed[f * HID + tid];
        const float bev = b_embed[tid];
        #pragma unroll
        for (int i = 0; i < NN; ++i) {
            float s = bev;
            #pragma unroll
            for (int f = 0; f < INDIM; ++f) s = fmaf(xs[i * INDIM + f], we[f], s);
            bufA[i * STRIDE + tid] = s;
        }
    }
    __syncthreads();

    // ---- agg1: bufB = adj @ bufA (column layout) ----
    #pragma unroll
    for (int i = 0; i < NN; ++i) {
        float s = 0.0f;
        #pragma unroll
        for (int r = 0; r < KNN; ++r) s += bufA[nbr[i * KNN + r] * STRIDE + tid];
        bufB[i * STRIDE + tid] = s;
    }
    __syncthreads();

    u64 acc[20];
    float v[20], m[5], rs[5];

    // ---- GEMM1: (5 rows x 4 cols)/thread, f32x2 packed ----
    gemm20(bufB, g_Wp1, r0, c0, acc);
    {
        float4 bb = *reinterpret_cast<const float4*>(&b1[c0]);
        float bias[4] = {bb.x, bb.y, bb.z, bb.w};
        #pragma unroll
        for (int i = 0; i < 20; ++i) {
            float2 f = *reinterpret_cast<float2*>(&acc[i]);
            v[i] = f.x + f.y + bias[i & 3];
        }
    }
    ln_warp(v, m, rs);

    // ---- LN1 + GeLU -> bufB (overwritten after all GEMM1 reads complete) ----
    __syncthreads();
    {
        float4 gg = *reinterpret_cast<const float4*>(&g1[c0]);
        float4 ee = *reinterpret_cast<const float4*>(&be1[c0]);
        float g[4] = {gg.x, gg.y, gg.z, gg.w};
        float e[4] = {ee.x, ee.y, ee.z, ee.w};
        #pragma unroll
        for (int r = 0; r < 5; ++r) {
            float4 h;
            float* hp = &h.x;
            #pragma unroll
            for (int c = 0; c < 4; ++c)
                hp[c] = gelu_exact(fmaf((v[r * 4 + c] - m[r]) * rs[r], g[c], e[c]));
            *reinterpret_cast<float4*>(&bufB[(r0 + r) * STRIDE + c0]) = h;
        }
    }
    __syncthreads();

    // ---- agg2: bufA = adj @ bufB ((r,c) layout) ----
    #pragma unroll
    for (int r = 0; r < 5; ++r) {
        const int i = r0 + r;
        float4 s = make_float4(0.f, 0.f, 0.f, 0.f);
        #pragma unroll
        for (int j = 0; j < KNN; ++j) {
            float4 a = *reinterpret_cast<const float4*>(&bufB[nbr[i * KNN + j] * STRIDE + c0]);
            s.x += a.x; s.y += a.y; s.z += a.z; s.w += a.w;
        }
        *reinterpret_cast<float4*>(&bufA[(r0 + r) * STRIDE + c0]) = s;
    }
    __syncthreads();

    // ---- GEMM2 ----
    gemm20(bufA, g_Wp2, r0, c0, acc);
    {
        float4 bb = *reinterpret_cast<const float4*>(&b2[c0]);
        float bias[4] = {bb.x, bb.y, bb.z, bb.w};
        #pragma unroll
        for (int i = 0; i < 20; ++i) {
            float2 f = *reinterpret_cast<float2*>(&acc[i]);
            v[i] = f.x + f.y + bias[i & 3];
        }
    }
    ln_warp(v, m, rs);

    // ---- LN2 + residual (h1 from bufB) + GeLU + per-column partial max ----
    {
        float4 gg = *reinterpret_cast<const float4*>(&g2[c0]);
        float4 ee = *reinterpret_cast<const float4*>(&be2[c0]);
        float g[4] = {gg.x, gg.y, gg.z, gg.w};
        float e[4] = {ee.x, ee.y, ee.z, ee.w};
        float cmax[4] = {-3.4e38f, -3.4e38f, -3.4e38f, -3.4e38f};
        #pragma unroll
        for (int r = 0; r < 5; ++r) {
            float4 h1 = *reinterpret_cast<const float4*>(&bufB[(r0 + r) * STRIDE + c0]);
            const float* h1p = &h1.x;
            #pragma unroll
            for (int c = 0; c < 4; ++c) {
                float ln = fmaf((v[r * 4 + c] - m[r]) * rs[r], g[c], e[c]);
                cmax[c] = fmaxf(cmax[c], gelu_exact(h1p[c] + ln));
            }
        }
        *reinterpret_cast<float4*>(&pmax[rt * HID + c0]) =
            make_float4(cmax[0], cmax[1], cmax[2], cmax[3]);
    }
    __syncthreads();

    // ---- cross-rowgroup max, column tid owns output ----
    {
        float mx = fmaxf(fmaxf(pmax[tid], pmax[HID + tid]),
                         fmaxf(pmax[2 * HID + tid], pmax[3 * HID + tid]));
        out[(size_t)b * HID + tid] = mx;
    }
}

extern "C" void kernel_launch(void* const* d_in, const int* in_sizes, int n_in,
                              void* d_out, int out_size) {
    const float* x_all   = (const float*)d_in[0];
    const float* w_embed = (const float*)d_in[1];
    const float* b_embed = (const float*)d_in[2];
    const float* w1      = (const float*)d_in[3];
    const float* b1      = (const float*)d_in[4];
    const float* w2      = (const float*)d_in[5];
    const float* b2      = (const float*)d_in[6];
    const float* g1      = (const float*)d_in[7];
    const float* be1     = (const float*)d_in[8];
    const float* g2      = (const float*)d_in[9];
    const float* be2     = (const float*)d_in[10];
    float* out = (float*)d_out;

    const int B = in_sizes[0] / (NN * INDIM);

    prep_weights<<<(64 * HID + 255) / 256, 256>>>(w1, w2);
    hbond_gnn_fused<<<B, 128>>>(x_all, w_embed, b_embed, b1, b2,
                                g1, be1, g2, be2, out);
}